// round 17
// baseline (speedup 1.0000x reference)
#include <cuda_runtime.h>
#include <cuda_bf16.h>
#include <cstdint>

#define T_DIM    168
#define C_DIM    1024
#define NSEQ     168
#define HORIZON  24
#define KPAD     176                 // 11 k-steps of 16
#define KSTEPS   11

#define NBLOCKS    740               // 148 SMs x 5 CTAs (one full wave)
#define NSLOTS     (NBLOCKS * 4)     // 2960 warp slots
#define NTILES     8192              // 256 b x 32 groups of 32 ch
#define NEXTRA     (NTILES - 2 * NSLOTS)   // 2272 third-tiles (Bresenham spread)

// ---- smem layout ----
// per-warp stage chunk: 16 rows x 144 B (128 B data + 16 B pad) = 2304 B
#define WROW_W      36               // words per padded row
#define WSTAGE_B    2304
#define NBUF        3
#define WREGION_B   (NBUF * WSTAGE_B)          // 6912 per warp
#define BFRAG_OFF   (4 * WREGION_B)            // 27648
#define BFRAG_U32   (2 * KSTEPS * 3 * 64)      // 4224 u32 = 16896 B
#define SBETA_OFF   (BFRAG_OFF + BFRAG_U32 * 4)     // 44544
#define WSPAD_OFF   (SBETA_OFF + HORIZON * 4)       // 44640, dedicated [280]
#define SMEM_BYTES  (WSPAD_OFF + 280 * 4)           // 45760 (5 CTAs/SM: 228.8KB)
#define CHUNK_GB    (16 * 4096)      // gmem bytes per 16-row chunk step

// =================== PTX helpers ===================
__device__ __forceinline__ void cp16(uint32_t saddr, const void* gptr) {
    asm volatile("cp.async.cg.shared.global [%0], [%1], 16;"
                 :: "r"(saddr), "l"(gptr));
}
__device__ __forceinline__ void cp_commit() {
    asm volatile("cp.async.commit_group;");
}
template<int N>
__device__ __forceinline__ void cp_wait() {
    asm volatile("cp.async.wait_group %0;" :: "n"(N) : "memory");
}
__device__ __forceinline__ uint32_t cvt2(float hi, float lo) {
    uint32_t r;
    asm("cvt.rn.bf16x2.f32 %0, %1, %2;" : "=r"(r) : "f"(hi), "f"(lo));
    return r;
}
__device__ __forceinline__ void split_pair(float v0, float v1,
                                           uint32_t& hp, uint32_t& lp) {
    hp = cvt2(v1, v0);
    float h1 = __uint_as_float(hp & 0xffff0000u);
    float h0 = __uint_as_float(hp << 16);
    lp = cvt2(v1 - h1, v0 - h0);
}
__device__ __forceinline__ void mma16816(float* c, const uint32_t* a,
                                         const uint32_t* b) {
    asm volatile(
        "mma.sync.aligned.m16n8k16.row.col.f32.bf16.bf16.f32 "
        "{%0,%1,%2,%3}, {%4,%5,%6,%7}, {%8,%9}, {%0,%1,%2,%3};"
        : "+f"(c[0]), "+f"(c[1]), "+f"(c[2]), "+f"(c[3])
        : "r"(a[0]), "r"(a[1]), "r"(a[2]), "r"(a[3]), "r"(b[0]), "r"(b[1]));
}
__device__ __forceinline__ void lds_v2(uint32_t& r0, uint32_t& r1, uint32_t addr) {
    asm volatile("ld.shared.v2.u32 {%0,%1}, [%2];"
                 : "=r"(r0), "=r"(r1) : "r"(addr));
}

// =================== 5-CTA/SM warp-tile kernel, phase-0 overlapped ==========
// Grid = 740 CTAs x 4 warps = 2960 warp slots, 20 warps/SM. Warp-tile = 32
// channels x 1 b x full K (11 chunks); 2 base tiles per warp + Bresenham
// extras. Phase 0 (88 threads, adjacent-column pairs, no shfl) runs while 3
// initial chunks per warp stream from DRAM. Phase 1: warp-private depth-3
// cp.async pipeline, refills issued at end of each chunk body.
__global__ __launch_bounds__(128, 5)
void ar_mma_kernel(const float* __restrict__ y,
                   const float* __restrict__ w,
                   const float* __restrict__ bias,
                   float* __restrict__ out) {
    extern __shared__ char sm[];
    const int tid   = threadIdx.x;
    const int wid   = tid >> 5;
    const int lane  = tid & 31;
    const int lane4 = lane & 3;
    const int laneg = lane >> 2;
    const uint32_t sb = (uint32_t)__cvta_generic_to_shared((void*)sm);

    uint32_t* bf = (uint32_t*)(sm + BFRAG_OFF);
    float* sbeta = (float*)(sm + SBETA_OFF);
    float* wsp   = (float*)(sm + WSPAD_OFF);     // [280] zero-padded w

    // tile id -> base pointer of its 32-channel slice (128 B rows, stride 4 KB)
    auto tile_base = [&](int t) -> const char* {
        return (const char*)y + (long long)(t >> 5) * (T_DIM * C_DIM * 4)
                              + (long long)(t & 31) * 128;
    };

    const int gwid  = blockIdx.x * 4 + wid;
    // Bresenham spread of the extra tiles across all warps
    const int hrank  = (int)(((unsigned)gwid * NEXTRA) / NSLOTS);
    const int hnext  = (int)(((unsigned)(gwid + 1) * NEXTRA) / NSLOTS);
    const int ntiles = 2 + (hnext - hrank);
    const int L      = ntiles * KSTEPS;
    const int tile3  = 2 * NSLOTS + hrank;

    const uint32_t wsb = sb + wid * WREGION_B;
    // hoisted per-lane chunk-copy offsets (j advances 4 rows)
    const uint32_t lsoff = (uint32_t)(lane >> 3) * 144 + (uint32_t)(lane & 7) * 16;
    const int      lgoff = (lane >> 3) * 4096 + (lane & 7) * 16;

    // per-warp chunk prefetch: 16 rows x 128 B -> padded 144 B smem rows
    auto issue_chunk = [&](const char* gsrc, int buf, int jmax) {
        uint32_t sdst = wsb + buf * WSTAGE_B + lsoff;
        const char* g = gsrc + lgoff;
#pragma unroll
        for (int j = 0; j < 4; ++j) {
            if (j < jmax) cp16(sdst, g);
            sdst += 4 * 144;
            g    += 4 * 4096;
        }
        cp_commit();
    };

    // ---- kick DRAM first: chunks 0,1,2 of this warp's first tile ----
    const char* tb0 = tile_base(gwid);
    issue_chunk(tb0,               0, 4);
    issue_chunk(tb0 + 1 * CHUNK_GB, 1, 4);
    issue_chunk(tb0 + 2 * CHUNK_GB, 2, 4);

    // ---- ws_pad[280]: w at [23..190], zeros elsewhere (single pass) ----
    for (int i = tid; i < 280; i += 128)
        wsp[i] = (i >= 23 && i < 191) ? w[i - 23] : 0.f;
    __syncthreads();

    // ================= phase 0: adjacent-pair recursion -> fragments ========
    if (tid < 88) {
        float wt[HORIZON];
#pragma unroll
        for (int j = 0; j < HORIZON; ++j) wt[j] = wsp[167 + j];   // w[144+j]

        const int te  = tid * 2;           // even column 0..174
        const int kt  = te >> 4;
        const int r   = (te >> 3) & 1;
        const int ln4 = (te & 7) >> 1;
        float ca[HORIZON], cb[HORIZON];
#pragma unroll
        for (int h = 0; h < HORIZON; ++h) {
            float a = wsp[23 + te - h];        // guard-free (padded)
            float b = wsp[24 + te - h];
#pragma unroll
            for (int j = 0; j < h; ++j) {
                a += wt[24 - h + j] * ca[j];
                b += wt[24 - h + j] * cb[j];
            }
            ca[h] = a;  cb[h] = b;
            uint32_t hp, lp;
            split_pair(a, b, hp, lp);
            int base = (kt * 3 + (h >> 3)) * 64 + ((h & 7) * 4 + ln4) * 2 + r;
            bf[base] = hp;
            bf[KSTEPS * 3 * 64 + base] = lp;
        }
    }
    if (tid == 127) {
        float wt[HORIZON];
#pragma unroll
        for (int j = 0; j < HORIZON; ++j) wt[j] = wsp[167 + j];
        float bb[HORIZON];
        float bv = __ldg(&bias[0]);
#pragma unroll
        for (int h = 0; h < HORIZON; ++h) {
            float acc = bv;
#pragma unroll
            for (int j = 0; j < h; ++j) acc += wt[24 - h + j] * bb[j];
            bb[h] = acc;
            sbeta[h] = acc;
        }
    }
    __syncthreads();      // last block barrier: fragments + beta visible

    // ================= phase 1: warp-private rolling tile stream ============
    const int t0 = lane4 * 2;
    const uint32_t bfb = sb + BFRAG_OFF + (uint32_t)lane * 8;   // B frag base

    // rolling prefetch state: next chunk to issue = global q=3 (tile gwid,
    // chunk 3) into buffer 0; refills happen at the END of each chunk body.
    int pt = gwid, pch = 3;
    const char* pg = tb0 + 3 * CHUNK_GB;
    int tile = gwid;
    int q = 0;

#pragma unroll 1
    for (int k = 0; k < ntiles; ++k) {
        float acc[2][3][4];
#pragma unroll
        for (int m = 0; m < 2; ++m)
#pragma unroll
            for (int n = 0; n < 3; ++n)
#pragma unroll
                for (int rr = 0; rr < 4; ++rr) acc[m][n][rr] = 0.f;

#pragma unroll 1
        for (int kt = 0; kt < KSTEPS; ++kt, ++q) {
            if      (q < L - 2)  { cp_wait<2>(); }
            else if (q == L - 2) { cp_wait<1>(); }
            else                 { cp_wait<0>(); }
            __syncwarp();

            uint32_t Bh[3][2], Bl[3][2];
            const uint32_t bk = bfb + (uint32_t)kt * 768;
#pragma unroll
            for (int nt = 0; nt < 3; ++nt) {
                lds_v2(Bh[nt][0], Bh[nt][1], bk + (uint32_t)nt * 256);
                lds_v2(Bl[nt][0], Bl[nt][1], bk + (uint32_t)nt * 256 + 8448);
            }

            // cbuf = q % 3 (tracked by pointer cycling)
            const float* pw = (const float*)(sm + wid * WREGION_B
                                                + (q % 3) * WSTAGE_B);
            const bool full = (kt < KSTEPS - 1);

#pragma unroll
            for (int m = 0; m < 2; ++m) {
                const float* p = pw + m * 16 + laneg;   // [t][ch]: stride 36 w

                float w00 = p[t0 * WROW_W],       w01 = p[(t0 + 1) * WROW_W];
                float w10 = p[t0 * WROW_W + 8],   w11 = p[(t0 + 1) * WROW_W + 8];

                uint32_t Ah[4], Al[4];
                split_pair(w00, w01, Ah[0], Al[0]);
                split_pair(w10, w11, Ah[1], Al[1]);
                if (full) {
                    float w02 = p[(t0 + 8) * WROW_W],     w03 = p[(t0 + 9) * WROW_W];
                    float w12 = p[(t0 + 8) * WROW_W + 8], w13 = p[(t0 + 9) * WROW_W + 8];
                    split_pair(w02, w03, Ah[2], Al[2]);
                    split_pair(w12, w13, Ah[3], Al[3]);
                } else {
                    Ah[2] = Ah[3] = Al[2] = Al[3] = 0u;   // t >= 168 contributes 0
                }

#pragma unroll
                for (int nt = 0; nt < 3; ++nt) {
                    mma16816(acc[m][nt], Ah, Bh[nt]);     // Ah*Bh
                    mma16816(acc[m][nt], Al, Bh[nt]);     // Al*Bh
                    mma16816(acc[m][nt], Ah, Bl[nt]);     // Ah*Bl
                }
            }

            // ---- refill: buffer q%3 is free now (its A data consumed) ----
            if (q + 3 < L) {
                issue_chunk(pg, q % 3, (pch == 10) ? 2 : 4);
                if (++pch == KSTEPS) {
                    pch = 0;
                    pt = (pt == gwid) ? gwid + NSLOTS : tile3;
                    pg = tile_base(pt);        // never consumed beyond L
                } else {
                    pg += CHUNK_GB;
                }
            }
        }

        // ---- per-tile epilogue (per-warp, overlaps in-flight loads) ----
        {
            const int bb = tile >> 5;
            const int c0 = (tile & 31) * 32;
            float* ob = out + (long long)bb * HORIZON * C_DIM + c0;
#pragma unroll
            for (int nt = 0; nt < 3; ++nt) {
                const int h0 = nt * 8 + lane4 * 2;
                const float be0 = sbeta[h0];
                const float be1 = sbeta[h0 + 1];
#pragma unroll
                for (int m = 0; m < 2; ++m) {
                    const int row = m * 16 + laneg;
                    ob[(long long)h0 * C_DIM + row]           = acc[m][nt][0] + be0;
                    ob[(long long)(h0 + 1) * C_DIM + row]     = acc[m][nt][1] + be1;
                    ob[(long long)h0 * C_DIM + row + 8]       = acc[m][nt][2] + be0;
                    ob[(long long)(h0 + 1) * C_DIM + row + 8] = acc[m][nt][3] + be1;
                }
            }
        }
        tile = (tile == gwid) ? gwid + NSLOTS : tile3;
    }
}

extern "C" void kernel_launch(void* const* d_in, const int* in_sizes, int n_in,
                              void* d_out, int out_size) {
    // metadata order: x (unused), y, w, b
    const float* y    = (const float*)d_in[1];
    const float* w    = (const float*)d_in[2];
    const float* bias = (const float*)d_in[3];
    float* out        = (float*)d_out;

    ar_mma_kernel<<<NBLOCKS, 128, SMEM_BYTES>>>(y, w, bias, out);
}